// round 8
// baseline (speedup 1.0000x reference)
#include <cuda_runtime.h>
#include <cuda_fp16.h>
#include <cstdint>

#define BATCH_ 128
#define TLEN   256
#define HID    2048
#define FOURH  8192
#define NSTEP  255
#define BK     64
#define NCHUNK 32          // HID / BK
#define NBLK   256         // 128 N-blocks x 2 M-blocks (64 rows each)

// ---------------- persistent device state (no cudaMalloc allowed) -----------
__device__ float g_c[BATCH_ * HID];
__device__ __half g_h_hi[2][BATCH_ * HID];   // h split-fp16, double-buffered
__device__ __half g_h_lo[2][BATCH_ * HID];
// Wh^T, gate-permuted, split-fp16: permuted col p = nb*64 + w_n*32 + gate*8 + q
__device__ __half g_W_hi[(size_t)FOURH * HID];
__device__ __half g_W_lo[(size_t)FOURH * HID];

// ---------------- helpers (all sm_80+ base-target PTX) ----------------------
__device__ __forceinline__ uint32_t sw128(uint32_t x) { return x ^ ((x >> 3) & 0x70); }

__device__ __forceinline__ uint32_t smem_u32(const void* p) {
    uint32_t a;
    asm("{ .reg .u64 t; cvta.to.shared.u64 t, %1; cvt.u32.u64 %0, t; }"
        : "=r"(a) : "l"(p));
    return a;
}

__device__ __forceinline__ void cp16(uint32_t d, const void* s) {
    asm volatile("cp.async.cg.shared.global [%0], [%1], 16;"
                 :: "r"(d), "l"(s) : "memory");
}

__device__ __forceinline__ void ldsm4(uint32_t* r, uint32_t a) {
    asm volatile("ldmatrix.sync.aligned.m8n8.x4.shared.b16 {%0,%1,%2,%3}, [%4];"
                 : "=r"(r[0]), "=r"(r[1]), "=r"(r[2]), "=r"(r[3]) : "r"(a));
}

__device__ __forceinline__ void mma16816(float* c, const uint32_t* a,
                                         uint32_t b0, uint32_t b1) {
    asm volatile(
        "mma.sync.aligned.m16n8k16.row.col.f32.f16.f16.f32 "
        "{%0,%1,%2,%3}, {%4,%5,%6,%7}, {%8,%9}, {%0,%1,%2,%3};"
        : "+f"(c[0]), "+f"(c[1]), "+f"(c[2]), "+f"(c[3])
        : "r"(a[0]), "r"(a[1]), "r"(a[2]), "r"(a[3]), "r"(b0), "r"(b1));
}

__device__ __forceinline__ float fast_sigmoid(float v) {
    return __fdividef(1.0f, 1.0f + __expf(-v));
}
__device__ __forceinline__ float fast_tanh(float v) {
    float a = fabsf(v);
    float t = __expf(-2.0f * a);
    float r = __fdividef(1.0f - t, 1.0f + t);
    return copysignf(r, v);
}

// smem stage layout (per 32KB stage): A_hi 8K | A_lo 8K | B_hi 8K | B_lo 8K
#define AHI_O 0
#define ALO_O 8192
#define BHI_O 16384
#define BLO_O 24576
#define STAGE_B 32768
#define NSTAGE 3
#define SMEM_TOTAL (NSTAGE * STAGE_B)   // 98304 per CTA; 2 CTAs/SM = 192K

// ---------------- init: coalesced tiled transpose of Wh into split fp16 -----
__global__ __launch_bounds__(256) void init_w_kernel(const float* __restrict__ Wh) {
    __shared__ float tile[64][65];
    const int cb = blockIdx.x >> 5;        // 0..127  (colp tile /64)
    const int kb = blockIdx.x & 31;        // 0..31   (k tile /64)
    const int tid = threadIdx.x;

    {
        const int k_local = tid >> 2;      // 0..63
        const int seg0 = tid & 3;
        const size_t krow = (size_t)(kb * 64 + k_local) * FOURH;
        #pragma unroll
        for (int ss = 0; ss < 2; ss++) {
            const int s = seg0 + ss * 4;   // 0..7
            const int w_n = s >> 2;
            const int gate = s & 3;
            const int base_o = gate * HID + cb * 16 + w_n * 8;
            const float4 v0 = *(const float4*)(Wh + krow + base_o);
            const float4 v1 = *(const float4*)(Wh + krow + base_o + 4);
            const int r0 = w_n * 32 + gate * 8;
            tile[r0 + 0][k_local] = v0.x;
            tile[r0 + 1][k_local] = v0.y;
            tile[r0 + 2][k_local] = v0.z;
            tile[r0 + 3][k_local] = v0.w;
            tile[r0 + 4][k_local] = v1.x;
            tile[r0 + 5][k_local] = v1.y;
            tile[r0 + 6][k_local] = v1.z;
            tile[r0 + 7][k_local] = v1.w;
        }
    }
    __syncthreads();

    {
        const int r  = tid >> 2;           // 0..63
        const int k0 = (tid & 3) * 16;
        const size_t obase = (size_t)(cb * 64 + r) * HID + kb * 64 + k0;
        __half hibuf[16], lobuf[16];
        #pragma unroll
        for (int i = 0; i < 16; i++) {
            const float v = tile[r][k0 + i];
            const __half hi = __float2half(v);
            hibuf[i] = hi;
            lobuf[i] = __float2half(v - __half2float(hi));
        }
        *(uint4*)(g_W_hi + obase)     = *(uint4*)(hibuf);
        *(uint4*)(g_W_hi + obase + 8) = *(uint4*)(hibuf + 8);
        *(uint4*)(g_W_lo + obase)     = *(uint4*)(lobuf);
        *(uint4*)(g_W_lo + obase + 8) = *(uint4*)(lobuf + 8);
    }
}

__global__ void zero_kernel() {
    const int n = BATCH_ * HID;
    for (int i = blockIdx.x * blockDim.x + threadIdx.x; i < n;
         i += gridDim.x * blockDim.x) {
        g_c[i] = 0.0f;
        g_h_hi[0][i] = __float2half(0.0f);
        g_h_lo[0][i] = __float2half(0.0f);
    }
}

// ---------------- one LSTM timestep ------------------------------------------
// Grid 256 = 128 N-blocks x 2 M-blocks. 2 CTAs co-resident per SM so one CTA's
// MMA covers the other's cp.async/barrier bubbles. Warp grid 4x2 of m16n32.
__global__ __launch_bounds__(256, 2) void step_kernel(
    const float* __restrict__ x, const float* __restrict__ Wx,
    const float* __restrict__ bvec, int t)
{
    extern __shared__ __align__(1024) unsigned char smem[];
    const uint32_t sb = smem_u32(smem);
    const int tid  = threadIdx.x;
    const int w    = tid >> 5;
    const int lane = tid & 31;
    const int w_m  = w >> 1;          // 0..3 (row group of 16)
    const int w_n  = w & 1;           // 0..1 (col group of 32)
    const int nblk = blockIdx.x >> 1;
    const int mblk = blockIdx.x & 1;
    const int row0 = mblk * 64;       // CTA's batch-row base

    const int par0 = t & 1;
    const int par1 = (t + 1) & 1;

    // -------- precomputed cp.async mappings (2 iters x 4 arrays) ------------
    // idx = tid + i*256 -> row = idx>>3 (0..63), kk = (idx&7)*8
    const int r0l = tid >> 3;
    const int kk0 = (tid & 7) * 8;
    const uint32_t so0 = sw128((uint32_t)r0l * 128 + kk0 * 2);
    const uint32_t so1 = sw128((uint32_t)(r0l + 32) * 128 + kk0 * 2);
    const __half* __restrict__ pAh = g_h_hi[par0] + (size_t)(row0 + r0l) * HID + kk0;
    const __half* __restrict__ pAl = g_h_lo[par0] + (size_t)(row0 + r0l) * HID + kk0;
    const __half* __restrict__ pBh = g_W_hi + (size_t)(nblk * 64 + r0l) * HID + kk0;
    const __half* __restrict__ pBl = g_W_lo + (size_t)(nblk * 64 + r0l) * HID + kk0;
    const size_t rstep = (size_t)32 * HID;

    // -------- hoisted epilogue operands --------------------------------------
    const int q2 = (lane & 3) * 2;
    const int hcol0 = nblk * 16 + w_n * 8 + q2;
    float wx[4][2], bb[4][2];
    #pragma unroll
    for (int g = 0; g < 4; g++) {
        const int o = g * HID + hcol0;
        wx[g][0] = Wx[o];     wx[g][1] = Wx[o + 1];
        bb[g][0] = bvec[o];   bb[g][1] = bvec[o + 1];
    }
    const int rbase = row0 + w_m * 16 + (lane >> 2);
    float xt[2];
    xt[0] = x[rbase * TLEN + t];
    xt[1] = x[(rbase + 8) * TLEN + t];

    // -------- precomputed ldsm swizzled base offsets --------------------------
    const int lm = lane & 15;
    const int lh = lane >> 4;
    const uint32_t kb_lane = (uint32_t)lh * 16;
    const uint32_t roAhi = (AHI_O + sw128((uint32_t)(w_m * 16 + lm) * 128)) ^ kb_lane;
    const uint32_t roAlo = (ALO_O + sw128((uint32_t)(w_m * 16 + lm) * 128)) ^ kb_lane;
    uint32_t roBhi[2], roBlo[2];
    #pragma unroll
    for (int g = 0; g < 2; g++) {
        const uint32_t s = sw128(((uint32_t)(w_n * 32 + lm) + g * 16) * 128);
        roBhi[g] = (BHI_O + s) ^ kb_lane;
        roBlo[g] = (BLO_O + s) ^ kb_lane;
    }

    float cacc[4][4];
    #pragma unroll
    for (int g = 0; g < 4; g++)
        #pragma unroll
        for (int i = 0; i < 4; i++) cacc[g][i] = 0.0f;

    auto issue_chunk = [&](uint32_t st, int c) {
        const int ko = c * BK;
        cp16(st + AHI_O + so0, pAh + ko);
        cp16(st + AHI_O + so1, pAh + ko + rstep);
        cp16(st + ALO_O + so0, pAl + ko);
        cp16(st + ALO_O + so1, pAl + ko + rstep);
        cp16(st + BHI_O + so0, pBh + ko);
        cp16(st + BHI_O + so1, pBh + ko + rstep);
        cp16(st + BLO_O + so0, pBl + ko);
        cp16(st + BLO_O + so1, pBl + ko + rstep);
        asm volatile("cp.async.commit_group;" ::: "memory");
    };

    // prologue: 2 chunks in flight
    issue_chunk(sb, 0);
    issue_chunk(sb + STAGE_B, 1);

    uint32_t stage = 0;     // stage holding chunk c
    uint32_t stage2 = 2;    // stage to fill with chunk c+2
    #pragma unroll 1
    for (int c = 0; c < NCHUNK; c++) {
        if (c < NCHUNK - 1)
            asm volatile("cp.async.wait_group 1;" ::: "memory");
        else
            asm volatile("cp.async.wait_group 0;" ::: "memory");
        __syncthreads();

        if (c + 2 < NCHUNK)
            issue_chunk(sb + stage2 * STAGE_B, c + 2);

        const uint32_t st = sb + stage * STAGE_B;
        #pragma unroll
        for (int ks = 0; ks < 4; ks++) {
            const uint32_t kx = (uint32_t)ks * 32;
            uint32_t ahi[4], alo[4], bhi[2][4], blo[2][4];
            ldsm4(ahi, st + (roAhi ^ kx));
            ldsm4(alo, st + (roAlo ^ kx));
            #pragma unroll
            for (int gg = 0; gg < 2; gg++) {
                ldsm4(bhi[gg], st + (roBhi[gg] ^ kx));
                ldsm4(blo[gg], st + (roBlo[gg] ^ kx));
            }
            #pragma unroll
            for (int g = 0; g < 4; g++) {
                const int gg = g >> 1, pr = g & 1;
                const uint32_t b0h = bhi[gg][pr], b1h = bhi[gg][pr + 2];
                const uint32_t b0l = blo[gg][pr], b1l = blo[gg][pr + 2];
                mma16816(cacc[g], ahi, b0h, b1h);   // hi*hi
                mma16816(cacc[g], ahi, b0l, b1l);   // hi*lo
                mma16816(cacc[g], alo, b0h, b1h);   // lo*hi
            }
        }
        stage  = (stage == NSTAGE - 1) ? 0 : stage + 1;
        stage2 = (stage2 == NSTAGE - 1) ? 0 : stage2 + 1;
    }

    // ---- fused LSTM epilogue: all 4 gates of (row, hcol) in this thread ----
    #pragma unroll
    for (int rh = 0; rh < 2; rh++) {
        const int row = rbase + rh * 8;
        const float xv = xt[rh];
        const size_t base = (size_t)row * HID + hcol0;
        const float2 cold = *(const float2*)(g_c + base);
        float hv[2], cv[2];
        #pragma unroll
        for (int e = 0; e < 2; e++) {
            const int ri = rh * 2 + e;
            const float zg = cacc[0][ri] + xv * wx[0][e] + bb[0][e];
            const float zi = cacc[1][ri] + xv * wx[1][e] + bb[1][e];
            const float zf = cacc[2][ri] + xv * wx[2][e] + bb[2][e];
            const float zo = cacc[3][ri] + xv * wx[3][e] + bb[3][e];
            const float gg = fast_tanh(zg);
            const float ii = fast_sigmoid(zi);
            const float ff = fast_sigmoid(zf);
            const float oo = fast_sigmoid(zo);
            const float co = (e == 0) ? cold.x : cold.y;
            cv[e] = gg * ii + co * ff;
            hv[e] = fast_tanh(cv[e]) * oo;
        }
        *(float2*)(g_c + base) = make_float2(cv[0], cv[1]);
        __half hh0 = __float2half(hv[0]);
        __half hh1 = __float2half(hv[1]);
        __half hl0 = __float2half(hv[0] - __half2float(hh0));
        __half hl1 = __float2half(hv[1] - __half2float(hh1));
        *(__half2*)(g_h_hi[par1] + base) = __halves2half2(hh0, hh1);
        *(__half2*)(g_h_lo[par1] + base) = __halves2half2(hl0, hl1);
    }
}

// ---------------- final projection + softmax ---------------------------------
__global__ void proj_kernel(const float* __restrict__ Wph,
                            const float* __restrict__ bp,
                            float* __restrict__ out)
{
    const int row = blockIdx.x;
    const int lane = threadIdx.x;
    const int par = NSTEP & 1;   // 1

    float acc = -1e30f;
    if (lane < 10) {
        acc = bp[lane];
        const size_t base = (size_t)row * HID;
        for (int k = 0; k < HID; k++) {
            const float hv = __half2float(g_h_hi[par][base + k]) +
                             __half2float(g_h_lo[par][base + k]);
            acc += hv * Wph[k * 10 + lane];
        }
    }
    float m = acc;
    #pragma unroll
    for (int off = 16; off > 0; off >>= 1)
        m = fmaxf(m, __shfl_xor_sync(0xffffffffu, m, off));
    float e = (lane < 10) ? __expf(acc - m) : 0.0f;
    float s = e;
    #pragma unroll
    for (int off = 16; off > 0; off >>= 1)
        s += __shfl_xor_sync(0xffffffffu, s, off);
    if (lane < 10) out[row * 10 + lane] = e / s;
}

extern "C" void kernel_launch(void* const* d_in, const int* in_sizes, int n_in,
                              void* d_out, int out_size) {
    (void)in_sizes; (void)n_in; (void)out_size;
    const float* x   = (const float*)d_in[0];
    const float* Wx  = (const float*)d_in[1];
    const float* Wh  = (const float*)d_in[2];
    const float* b   = (const float*)d_in[3];
    const float* Wph = (const float*)d_in[4];
    const float* bp  = (const float*)d_in[5];
    float* out = (float*)d_out;

    static int attr_set = 0;
    if (!attr_set) {
        cudaFuncSetAttribute(step_kernel,
                             cudaFuncAttributeMaxDynamicSharedMemorySize,
                             SMEM_TOTAL);
        attr_set = 1;
    }

    init_w_kernel<<<4096, 256>>>(Wh);
    zero_kernel<<<256, 256>>>();
    for (int t = 0; t < NSTEP; t++) {
        step_kernel<<<NBLK, 256, SMEM_TOTAL>>>(x, Wx, b, t);
    }
    proj_kernel<<<BATCH_, 32>>>(Wph, bp, out);
}

// round 9
// speedup vs baseline: 1.3962x; 1.3962x over previous
#include <cuda_runtime.h>
#include <cuda_fp16.h>
#include <cstdint>

#define BATCH_ 128
#define TLEN   256
#define HID    2048
#define FOURH  8192
#define NSTEP  255
#define BK     64
#define NCHUNK 32          // HID / BK
#define NBLK   256         // 128 N-blocks x 2 M-blocks (64 rows each)

// ---------------- persistent device state (no cudaMalloc allowed) -----------
__device__ float g_c[BATCH_ * HID];
__device__ __half g_h_hi[2][BATCH_ * HID];   // h quantized to fp16, double-buffered
// Wh^T, gate-permuted, split-fp16 (W kept to ~22 bits via hi+lo):
// permuted col p = nb*64 + w_n*32 + gate*8 + q
__device__ __half g_W_hi[(size_t)FOURH * HID];
__device__ __half g_W_lo[(size_t)FOURH * HID];

// ---------------- helpers (all sm_80+ base-target PTX) ----------------------
__device__ __forceinline__ uint32_t sw128(uint32_t x) { return x ^ ((x >> 3) & 0x70); }

__device__ __forceinline__ uint32_t smem_u32(const void* p) {
    uint32_t a;
    asm("{ .reg .u64 t; cvta.to.shared.u64 t, %1; cvt.u32.u64 %0, t; }"
        : "=r"(a) : "l"(p));
    return a;
}

__device__ __forceinline__ void cp16(uint32_t d, const void* s) {
    asm volatile("cp.async.cg.shared.global [%0], [%1], 16;"
                 :: "r"(d), "l"(s) : "memory");
}

__device__ __forceinline__ void ldsm4(uint32_t* r, uint32_t a) {
    asm volatile("ldmatrix.sync.aligned.m8n8.x4.shared.b16 {%0,%1,%2,%3}, [%4];"
                 : "=r"(r[0]), "=r"(r[1]), "=r"(r[2]), "=r"(r[3]) : "r"(a));
}

__device__ __forceinline__ void mma16816(float* c, const uint32_t* a,
                                         uint32_t b0, uint32_t b1) {
    asm volatile(
        "mma.sync.aligned.m16n8k16.row.col.f32.f16.f16.f32 "
        "{%0,%1,%2,%3}, {%4,%5,%6,%7}, {%8,%9}, {%0,%1,%2,%3};"
        : "+f"(c[0]), "+f"(c[1]), "+f"(c[2]), "+f"(c[3])
        : "r"(a[0]), "r"(a[1]), "r"(a[2]), "r"(a[3]), "r"(b0), "r"(b1));
}

__device__ __forceinline__ float fast_sigmoid(float v) {
    return __fdividef(1.0f, 1.0f + __expf(-v));
}
__device__ __forceinline__ float fast_tanh(float v) {
    float a = fabsf(v);
    float t = __expf(-2.0f * a);
    float r = __fdividef(1.0f - t, 1.0f + t);
    return copysignf(r, v);
}

// smem stage layout (per 24KB stage): A_hi 8K | B_hi 8K | B_lo 8K
#define AHI_O 0
#define BHI_O 8192
#define BLO_O 16384
#define STAGE_B 24576
#define NSTAGE 3
#define SMEM_TOTAL (NSTAGE * STAGE_B)   // 73728 per CTA; 2 CTAs/SM

// ---------------- init: coalesced tiled transpose of Wh into split fp16 -----
__global__ __launch_bounds__(256) void init_w_kernel(const float* __restrict__ Wh) {
    __shared__ float tile[64][65];
    const int cb = blockIdx.x >> 5;        // 0..127  (colp tile /64)
    const int kb = blockIdx.x & 31;        // 0..31   (k tile /64)
    const int tid = threadIdx.x;

    {
        const int k_local = tid >> 2;      // 0..63
        const int seg0 = tid & 3;
        const size_t krow = (size_t)(kb * 64 + k_local) * FOURH;
        #pragma unroll
        for (int ss = 0; ss < 2; ss++) {
            const int s = seg0 + ss * 4;   // 0..7
            const int w_n = s >> 2;
            const int gate = s & 3;
            const int base_o = gate * HID + cb * 16 + w_n * 8;
            const float4 v0 = *(const float4*)(Wh + krow + base_o);
            const float4 v1 = *(const float4*)(Wh + krow + base_o + 4);
            const int r0 = w_n * 32 + gate * 8;
            tile[r0 + 0][k_local] = v0.x;
            tile[r0 + 1][k_local] = v0.y;
            tile[r0 + 2][k_local] = v0.z;
            tile[r0 + 3][k_local] = v0.w;
            tile[r0 + 4][k_local] = v1.x;
            tile[r0 + 5][k_local] = v1.y;
            tile[r0 + 6][k_local] = v1.z;
            tile[r0 + 7][k_local] = v1.w;
        }
    }
    __syncthreads();

    {
        const int r  = tid >> 2;           // 0..63
        const int k0 = (tid & 3) * 16;
        const size_t obase = (size_t)(cb * 64 + r) * HID + kb * 64 + k0;
        __half hibuf[16], lobuf[16];
        #pragma unroll
        for (int i = 0; i < 16; i++) {
            const float v = tile[r][k0 + i];
            const __half hi = __float2half(v);
            hibuf[i] = hi;
            lobuf[i] = __float2half(v - __half2float(hi));
        }
        *(uint4*)(g_W_hi + obase)     = *(uint4*)(hibuf);
        *(uint4*)(g_W_hi + obase + 8) = *(uint4*)(hibuf + 8);
        *(uint4*)(g_W_lo + obase)     = *(uint4*)(lobuf);
        *(uint4*)(g_W_lo + obase + 8) = *(uint4*)(lobuf + 8);
    }
}

__global__ void zero_kernel() {
    const int n = BATCH_ * HID;
    for (int i = blockIdx.x * blockDim.x + threadIdx.x; i < n;
         i += gridDim.x * blockDim.x) {
        g_c[i] = 0.0f;
        g_h_hi[0][i] = __float2half(0.0f);
    }
}

// ---------------- one LSTM timestep ------------------------------------------
// z = h_hi @ (W_hi + W_lo): exact-W / fp16-quantized-h 2-term scheme.
// Grid 256 = 128 N-blocks x 2 M-blocks; 2 CTAs/SM. Warp grid 4x2 of m16n32.
__global__ __launch_bounds__(256, 2) void step_kernel(
    const float* __restrict__ x, const float* __restrict__ Wx,
    const float* __restrict__ bvec, int t)
{
    extern __shared__ __align__(1024) unsigned char smem[];
    const uint32_t sb = smem_u32(smem);
    const int tid  = threadIdx.x;
    const int w    = tid >> 5;
    const int lane = tid & 31;
    const int w_m  = w >> 1;          // 0..3 (row group of 16)
    const int w_n  = w & 1;           // 0..1 (col group of 32)
    const int nblk = blockIdx.x >> 1;
    const int mblk = blockIdx.x & 1;
    const int row0 = mblk * 64;       // CTA's batch-row base

    const int par0 = t & 1;
    const int par1 = (t + 1) & 1;

    // -------- precomputed cp.async mappings ----------------------------------
    const int r0l = tid >> 3;                 // 0..31
    const int kk0 = (tid & 7) * 8;
    const uint32_t so0 = sw128((uint32_t)r0l * 128 + kk0 * 2);
    const uint32_t so1 = sw128((uint32_t)(r0l + 32) * 128 + kk0 * 2);
    const __half* __restrict__ pAh = g_h_hi[par0] + (size_t)(row0 + r0l) * HID + kk0;
    const __half* __restrict__ pBh = g_W_hi + (size_t)(nblk * 64 + r0l) * HID + kk0;
    const __half* __restrict__ pBl = g_W_lo + (size_t)(nblk * 64 + r0l) * HID + kk0;
    const size_t rstep = (size_t)32 * HID;

    // -------- hoisted epilogue operands --------------------------------------
    const int q2 = (lane & 3) * 2;
    const int hcol0 = nblk * 16 + w_n * 8 + q2;
    float wx[4][2], bb[4][2];
    #pragma unroll
    for (int g = 0; g < 4; g++) {
        const int o = g * HID + hcol0;
        wx[g][0] = Wx[o];     wx[g][1] = Wx[o + 1];
        bb[g][0] = bvec[o];   bb[g][1] = bvec[o + 1];
    }
    const int rbase = row0 + w_m * 16 + (lane >> 2);
    float xt[2];
    xt[0] = x[rbase * TLEN + t];
    xt[1] = x[(rbase + 8) * TLEN + t];

    // -------- precomputed ldsm swizzled base offsets --------------------------
    const int lm = lane & 15;
    const int lh = lane >> 4;
    const uint32_t kb_lane = (uint32_t)lh * 16;
    const uint32_t roAhi = (AHI_O + sw128((uint32_t)(w_m * 16 + lm) * 128)) ^ kb_lane;
    uint32_t roBhi[2], roBlo[2];
    #pragma unroll
    for (int g = 0; g < 2; g++) {
        const uint32_t s = sw128(((uint32_t)(w_n * 32 + lm) + g * 16) * 128);
        roBhi[g] = (BHI_O + s) ^ kb_lane;
        roBlo[g] = (BLO_O + s) ^ kb_lane;
    }

    float cacc[4][4];
    #pragma unroll
    for (int g = 0; g < 4; g++)
        #pragma unroll
        for (int i = 0; i < 4; i++) cacc[g][i] = 0.0f;

    auto issue_chunk = [&](uint32_t st, int c) {
        const int ko = c * BK;
        cp16(st + AHI_O + so0, pAh + ko);
        cp16(st + AHI_O + so1, pAh + ko + rstep);
        cp16(st + BHI_O + so0, pBh + ko);
        cp16(st + BHI_O + so1, pBh + ko + rstep);
        cp16(st + BLO_O + so0, pBl + ko);
        cp16(st + BLO_O + so1, pBl + ko + rstep);
        asm volatile("cp.async.commit_group;" ::: "memory");
    };

    // prologue: 2 chunks in flight
    issue_chunk(sb, 0);
    issue_chunk(sb + STAGE_B, 1);

    uint32_t stage = 0;     // stage holding chunk c
    uint32_t stage2 = 2;    // stage to fill with chunk c+2
    #pragma unroll 1
    for (int c = 0; c < NCHUNK; c++) {
        if (c < NCHUNK - 1)
            asm volatile("cp.async.wait_group 1;" ::: "memory");
        else
            asm volatile("cp.async.wait_group 0;" ::: "memory");
        __syncthreads();

        if (c + 2 < NCHUNK)
            issue_chunk(sb + stage2 * STAGE_B, c + 2);

        const uint32_t st = sb + stage * STAGE_B;
        #pragma unroll
        for (int ks = 0; ks < 4; ks++) {
            const uint32_t kx = (uint32_t)ks * 32;
            uint32_t ahi[4], bhi[2][4], blo[2][4];
            ldsm4(ahi, st + (roAhi ^ kx));
            #pragma unroll
            for (int gg = 0; gg < 2; gg++) {
                ldsm4(bhi[gg], st + (roBhi[gg] ^ kx));
                ldsm4(blo[gg], st + (roBlo[gg] ^ kx));
            }
            #pragma unroll
            for (int g = 0; g < 4; g++) {
                const int gg = g >> 1, pr = g & 1;
                mma16816(cacc[g], ahi, bhi[gg][pr], bhi[gg][pr + 2]);  // h*W_hi
                mma16816(cacc[g], ahi, blo[gg][pr], blo[gg][pr + 2]);  // h*W_lo
            }
        }
        stage  = (stage == NSTAGE - 1) ? 0 : stage + 1;
        stage2 = (stage2 == NSTAGE - 1) ? 0 : stage2 + 1;
    }

    // ---- fused LSTM epilogue: all 4 gates of (row, hcol) in this thread ----
    #pragma unroll
    for (int rh = 0; rh < 2; rh++) {
        const int row = rbase + rh * 8;
        const float xv = xt[rh];
        const size_t base = (size_t)row * HID + hcol0;
        const float2 cold = *(const float2*)(g_c + base);
        float hv[2], cv[2];
        #pragma unroll
        for (int e = 0; e < 2; e++) {
            const int ri = rh * 2 + e;
            const float zg = cacc[0][ri] + xv * wx[0][e] + bb[0][e];
            const float zi = cacc[1][ri] + xv * wx[1][e] + bb[1][e];
            const float zf = cacc[2][ri] + xv * wx[2][e] + bb[2][e];
            const float zo = cacc[3][ri] + xv * wx[3][e] + bb[3][e];
            const float gg = fast_tanh(zg);
            const float ii = fast_sigmoid(zi);
            const float ff = fast_sigmoid(zf);
            const float oo = fast_sigmoid(zo);
            const float co = (e == 0) ? cold.x : cold.y;
            cv[e] = gg * ii + co * ff;
            hv[e] = fast_tanh(cv[e]) * oo;
        }
        *(float2*)(g_c + base) = make_float2(cv[0], cv[1]);
        *(__half2*)(g_h_hi[par1] + base) =
            __halves2half2(__float2half(hv[0]), __float2half(hv[1]));
    }
}

// ---------------- final projection + softmax ---------------------------------
__global__ void proj_kernel(const float* __restrict__ Wph,
                            const float* __restrict__ bp,
                            float* __restrict__ out)
{
    const int row = blockIdx.x;
    const int lane = threadIdx.x;
    const int par = NSTEP & 1;   // 1

    float acc = -1e30f;
    if (lane < 10) {
        acc = bp[lane];
        const size_t base = (size_t)row * HID;
        for (int k = 0; k < HID; k++) {
            acc += __half2float(g_h_hi[par][base + k]) * Wph[k * 10 + lane];
        }
    }
    float m = acc;
    #pragma unroll
    for (int off = 16; off > 0; off >>= 1)
        m = fmaxf(m, __shfl_xor_sync(0xffffffffu, m, off));
    float e = (lane < 10) ? __expf(acc - m) : 0.0f;
    float s = e;
    #pragma unroll
    for (int off = 16; off > 0; off >>= 1)
        s += __shfl_xor_sync(0xffffffffu, s, off);
    if (lane < 10) out[row * 10 + lane] = e / s;
}

extern "C" void kernel_launch(void* const* d_in, const int* in_sizes, int n_in,
                              void* d_out, int out_size) {
    (void)in_sizes; (void)n_in; (void)out_size;
    const float* x   = (const float*)d_in[0];
    const float* Wx  = (const float*)d_in[1];
    const float* Wh  = (const float*)d_in[2];
    const float* b   = (const float*)d_in[3];
    const float* Wph = (const float*)d_in[4];
    const float* bp  = (const float*)d_in[5];
    float* out = (float*)d_out;

    static int attr_set = 0;
    if (!attr_set) {
        cudaFuncSetAttribute(step_kernel,
                             cudaFuncAttributeMaxDynamicSharedMemorySize,
                             SMEM_TOTAL);
        attr_set = 1;
    }

    init_w_kernel<<<4096, 256>>>(Wh);
    zero_kernel<<<256, 256>>>();
    for (int t = 0; t < NSTEP; t++) {
        step_kernel<<<NBLK, 256, SMEM_TOTAL>>>(x, Wx, b, t);
    }
    proj_kernel<<<BATCH_, 32>>>(Wph, bp, out);
}

// round 10
// speedup vs baseline: 2.0797x; 1.4895x over previous
#include <cuda_runtime.h>
#include <cuda_fp16.h>
#include <cstdint>

#define BATCH_ 128
#define TLEN   256
#define HID    2048
#define FOURH  8192
#define NSTEP  255
#define BK     64
#define NCHUNK 32          // HID / BK
#define NBLK   256         // 128 N-blocks x 2 M-blocks (64 rows each)

// ---------------- persistent device state (no cudaMalloc allowed) -----------
__device__ float g_c[BATCH_ * HID];
__device__ __half g_h_hi[2][BATCH_ * HID];   // h quantized to fp16, double-buffered
// Wh^T, gate-permuted, fp16: permuted col p = nb*64 + w_n*32 + gate*8 + q
__device__ __half g_W_hi[(size_t)FOURH * HID];

// ---------------- helpers (all sm_80+ base-target PTX) ----------------------
__device__ __forceinline__ uint32_t sw128(uint32_t x) { return x ^ ((x >> 3) & 0x70); }

__device__ __forceinline__ uint32_t smem_u32(const void* p) {
    uint32_t a;
    asm("{ .reg .u64 t; cvta.to.shared.u64 t, %1; cvt.u32.u64 %0, t; }"
        : "=r"(a) : "l"(p));
    return a;
}

__device__ __forceinline__ void cp16(uint32_t d, const void* s) {
    asm volatile("cp.async.cg.shared.global [%0], [%1], 16;"
                 :: "r"(d), "l"(s) : "memory");
}

__device__ __forceinline__ void ldsm4(uint32_t* r, uint32_t a) {
    asm volatile("ldmatrix.sync.aligned.m8n8.x4.shared.b16 {%0,%1,%2,%3}, [%4];"
                 : "=r"(r[0]), "=r"(r[1]), "=r"(r[2]), "=r"(r[3]) : "r"(a));
}

__device__ __forceinline__ void mma16816(float* c, const uint32_t* a,
                                         uint32_t b0, uint32_t b1) {
    asm volatile(
        "mma.sync.aligned.m16n8k16.row.col.f32.f16.f16.f32 "
        "{%0,%1,%2,%3}, {%4,%5,%6,%7}, {%8,%9}, {%0,%1,%2,%3};"
        : "+f"(c[0]), "+f"(c[1]), "+f"(c[2]), "+f"(c[3])
        : "r"(a[0]), "r"(a[1]), "r"(a[2]), "r"(a[3]), "r"(b0), "r"(b1));
}

__device__ __forceinline__ float fast_sigmoid(float v) {
    return __fdividef(1.0f, 1.0f + __expf(-v));
}
__device__ __forceinline__ float fast_tanh(float v) {
    float a = fabsf(v);
    float t = __expf(-2.0f * a);
    float r = __fdividef(1.0f - t, 1.0f + t);
    return copysignf(r, v);
}

// smem stage layout (per 16KB stage): A_hi 8K | B_hi 8K
#define AHI_O 0
#define BHI_O 8192
#define STAGE_B 16384
#define NSTAGE 4
#define SMEM_TOTAL (NSTAGE * STAGE_B)   // 65536 per CTA; 2 CTAs/SM = 128K

// ---------------- init: coalesced tiled transpose of Wh into fp16 -----------
__global__ __launch_bounds__(256) void init_w_kernel(const float* __restrict__ Wh) {
    __shared__ float tile[64][65];
    const int cb = blockIdx.x >> 5;        // 0..127  (colp tile /64)
    const int kb = blockIdx.x & 31;        // 0..31   (k tile /64)
    const int tid = threadIdx.x;

    {
        const int k_local = tid >> 2;      // 0..63
        const int seg0 = tid & 3;
        const size_t krow = (size_t)(kb * 64 + k_local) * FOURH;
        #pragma unroll
        for (int ss = 0; ss < 2; ss++) {
            const int s = seg0 + ss * 4;   // 0..7
            const int w_n = s >> 2;
            const int gate = s & 3;
            const int base_o = gate * HID + cb * 16 + w_n * 8;
            const float4 v0 = *(const float4*)(Wh + krow + base_o);
            const float4 v1 = *(const float4*)(Wh + krow + base_o + 4);
            const int r0 = w_n * 32 + gate * 8;
            tile[r0 + 0][k_local] = v0.x;
            tile[r0 + 1][k_local] = v0.y;
            tile[r0 + 2][k_local] = v0.z;
            tile[r0 + 3][k_local] = v0.w;
            tile[r0 + 4][k_local] = v1.x;
            tile[r0 + 5][k_local] = v1.y;
            tile[r0 + 6][k_local] = v1.z;
            tile[r0 + 7][k_local] = v1.w;
        }
    }
    __syncthreads();

    {
        const int r  = tid >> 2;           // 0..63
        const int k0 = (tid & 3) * 16;
        const size_t obase = (size_t)(cb * 64 + r) * HID + kb * 64 + k0;
        __half hibuf[16];
        #pragma unroll
        for (int i = 0; i < 16; i++)
            hibuf[i] = __float2half(tile[r][k0 + i]);
        *(uint4*)(g_W_hi + obase)     = *(uint4*)(hibuf);
        *(uint4*)(g_W_hi + obase + 8) = *(uint4*)(hibuf + 8);
    }
}

__global__ void zero_kernel() {
    const int n = BATCH_ * HID;
    for (int i = blockIdx.x * blockDim.x + threadIdx.x; i < n;
         i += gridDim.x * blockDim.x) {
        g_c[i] = 0.0f;
        g_h_hi[0][i] = __float2half(0.0f);
    }
}

// ---------------- one LSTM timestep ------------------------------------------
// z = h_fp16 @ W_fp16 (single term, fp32 accum).
// Grid 256 = 128 N-blocks x 2 M-blocks; 2 CTAs/SM. Warp grid 4x2 of m16n32.
__global__ __launch_bounds__(256, 2) void step_kernel(
    const float* __restrict__ x, const float* __restrict__ Wx,
    const float* __restrict__ bvec, int t)
{
    extern __shared__ __align__(1024) unsigned char smem[];
    const uint32_t sb = smem_u32(smem);
    const int tid  = threadIdx.x;
    const int w    = tid >> 5;
    const int lane = tid & 31;
    const int w_m  = w >> 1;          // 0..3 (row group of 16)
    const int w_n  = w & 1;           // 0..1 (col group of 32)
    const int nblk = blockIdx.x >> 1;
    const int mblk = blockIdx.x & 1;
    const int row0 = mblk * 64;       // CTA's batch-row base

    const int par0 = t & 1;
    const int par1 = (t + 1) & 1;

    // -------- precomputed cp.async mappings ----------------------------------
    const int r0l = tid >> 3;                 // 0..31
    const int kk0 = (tid & 7) * 8;
    const uint32_t so0 = sw128((uint32_t)r0l * 128 + kk0 * 2);
    const uint32_t so1 = sw128((uint32_t)(r0l + 32) * 128 + kk0 * 2);
    const __half* __restrict__ pAh = g_h_hi[par0] + (size_t)(row0 + r0l) * HID + kk0;
    const __half* __restrict__ pBh = g_W_hi + (size_t)(nblk * 64 + r0l) * HID + kk0;
    const size_t rstep = (size_t)32 * HID;

    // -------- hoisted epilogue operands --------------------------------------
    const int q2 = (lane & 3) * 2;
    const int hcol0 = nblk * 16 + w_n * 8 + q2;
    float wx[4][2], bb[4][2];
    #pragma unroll
    for (int g = 0; g < 4; g++) {
        const int o = g * HID + hcol0;
        wx[g][0] = Wx[o];     wx[g][1] = Wx[o + 1];
        bb[g][0] = bvec[o];   bb[g][1] = bvec[o + 1];
    }
    const int rbase = row0 + w_m * 16 + (lane >> 2);
    float xt[2];
    xt[0] = x[rbase * TLEN + t];
    xt[1] = x[(rbase + 8) * TLEN + t];

    // -------- precomputed ldsm swizzled base offsets --------------------------
    const int lm = lane & 15;
    const int lh = lane >> 4;
    const uint32_t kb_lane = (uint32_t)lh * 16;
    const uint32_t roAhi = (AHI_O + sw128((uint32_t)(w_m * 16 + lm) * 128)) ^ kb_lane;
    uint32_t roBhi[2];
    #pragma unroll
    for (int g = 0; g < 2; g++) {
        const uint32_t s = sw128(((uint32_t)(w_n * 32 + lm) + g * 16) * 128);
        roBhi[g] = (BHI_O + s) ^ kb_lane;
    }

    float cacc[4][4];
    #pragma unroll
    for (int g = 0; g < 4; g++)
        #pragma unroll
        for (int i = 0; i < 4; i++) cacc[g][i] = 0.0f;

    auto issue_chunk = [&](uint32_t st, int c) {
        const int ko = c * BK;
        cp16(st + AHI_O + so0, pAh + ko);
        cp16(st + AHI_O + so1, pAh + ko + rstep);
        cp16(st + BHI_O + so0, pBh + ko);
        cp16(st + BHI_O + so1, pBh + ko + rstep);
        asm volatile("cp.async.commit_group;" ::: "memory");
    };

    // prologue: 3 chunks in flight (4 stages, skew 3)
    issue_chunk(sb, 0);
    issue_chunk(sb + STAGE_B, 1);
    issue_chunk(sb + 2 * STAGE_B, 2);

    uint32_t stage = 0;     // stage holding chunk c
    uint32_t stage2 = 3;    // stage to fill with chunk c+3
    #pragma unroll 1
    for (int c = 0; c < NCHUNK; c++) {
        if (c < NCHUNK - 2)
            asm volatile("cp.async.wait_group 2;" ::: "memory");
        else if (c == NCHUNK - 2)
            asm volatile("cp.async.wait_group 1;" ::: "memory");
        else
            asm volatile("cp.async.wait_group 0;" ::: "memory");
        __syncthreads();

        if (c + 3 < NCHUNK)
            issue_chunk(sb + stage2 * STAGE_B, c + 3);

        const uint32_t st = sb + stage * STAGE_B;
        #pragma unroll
        for (int ks = 0; ks < 4; ks++) {
            const uint32_t kx = (uint32_t)ks * 32;
            uint32_t ahi[4], bhi[2][4];
            ldsm4(ahi, st + (roAhi ^ kx));
            #pragma unroll
            for (int gg = 0; gg < 2; gg++)
                ldsm4(bhi[gg], st + (roBhi[gg] ^ kx));
            #pragma unroll
            for (int g = 0; g < 4; g++) {
                const int gg = g >> 1, pr = g & 1;
                mma16816(cacc[g], ahi, bhi[gg][pr], bhi[gg][pr + 2]);
            }
        }
        stage  = (stage == NSTAGE - 1) ? 0 : stage + 1;
        stage2 = (stage2 == NSTAGE - 1) ? 0 : stage2 + 1;
    }

    // ---- fused LSTM epilogue: all 4 gates of (row, hcol) in this thread ----
    #pragma unroll
    for (int rh = 0; rh < 2; rh++) {
        const int row = rbase + rh * 8;
        const float xv = xt[rh];
        const size_t base = (size_t)row * HID + hcol0;
        const float2 cold = *(const float2*)(g_c + base);
        float hv[2], cv[2];
        #pragma unroll
        for (int e = 0; e < 2; e++) {
            const int ri = rh * 2 + e;
            const float zg = cacc[0][ri] + xv * wx[0][e] + bb[0][e];
            const float zi = cacc[1][ri] + xv * wx[1][e] + bb[1][e];
            const float zf = cacc[2][ri] + xv * wx[2][e] + bb[2][e];
            const float zo = cacc[3][ri] + xv * wx[3][e] + bb[3][e];
            const float gg = fast_tanh(zg);
            const float ii = fast_sigmoid(zi);
            const float ff = fast_sigmoid(zf);
            const float oo = fast_sigmoid(zo);
            const float co = (e == 0) ? cold.x : cold.y;
            cv[e] = gg * ii + co * ff;
            hv[e] = fast_tanh(cv[e]) * oo;
        }
        *(float2*)(g_c + base) = make_float2(cv[0], cv[1]);
        *(__half2*)(g_h_hi[par1] + base) =
            __halves2half2(__float2half(hv[0]), __float2half(hv[1]));
    }
}

// ---------------- final projection + softmax ---------------------------------
__global__ void proj_kernel(const float* __restrict__ Wph,
                            const float* __restrict__ bp,
                            float* __restrict__ out)
{
    const int row = blockIdx.x;
    const int lane = threadIdx.x;
    const int par = NSTEP & 1;   // 1

    float acc = -1e30f;
    if (lane < 10) {
        acc = bp[lane];
        const size_t base = (size_t)row * HID;
        for (int k = 0; k < HID; k++) {
            acc += __half2float(g_h_hi[par][base + k]) * Wph[k * 10 + lane];
        }
    }
    float m = acc;
    #pragma unroll
    for (int off = 16; off > 0; off >>= 1)
        m = fmaxf(m, __shfl_xor_sync(0xffffffffu, m, off));
    float e = (lane < 10) ? __expf(acc - m) : 0.0f;
    float s = e;
    #pragma unroll
    for (int off = 16; off > 0; off >>= 1)
        s += __shfl_xor_sync(0xffffffffu, s, off);
    if (lane < 10) out[row * 10 + lane] = e / s;
}

extern "C" void kernel_launch(void* const* d_in, const int* in_sizes, int n_in,
                              void* d_out, int out_size) {
    (void)in_sizes; (void)n_in; (void)out_size;
    const float* x   = (const float*)d_in[0];
    const float* Wx  = (const float*)d_in[1];
    const float* Wh  = (const float*)d_in[2];
    const float* b   = (const float*)d_in[3];
    const float* Wph = (const float*)d_in[4];
    const float* bp  = (const float*)d_in[5];
    float* out = (float*)d_out;

    static int attr_set = 0;
    if (!attr_set) {
        cudaFuncSetAttribute(step_kernel,
                             cudaFuncAttributeMaxDynamicSharedMemorySize,
                             SMEM_TOTAL);
        attr_set = 1;
    }

    init_w_kernel<<<4096, 256>>>(Wh);
    zero_kernel<<<256, 256>>>();
    for (int t = 0; t < NSTEP; t++) {
        step_kernel<<<NBLK, 256, SMEM_TOTAL>>>(x, Wx, b, t);
    }
    proj_kernel<<<BATCH_, 32>>>(Wph, bp, out);
}

// round 11
// speedup vs baseline: 2.4643x; 1.1850x over previous
#include <cuda_runtime.h>
#include <cuda_fp16.h>
#include <cstdint>

#define BATCH_ 128
#define TLEN   256
#define HID    2048
#define FOURH  8192
#define NSTEP  255
#define BKC    128         // k per pipeline iteration (2 x 64 sub-tiles)
#define NCHUNK 16          // HID / BKC
#define NBLK   256         // 128 N-blocks x 2 M-blocks (64 rows each)

// ---------------- persistent device state (no cudaMalloc allowed) -----------
__device__ float g_c[BATCH_ * HID];
__device__ __half g_h_hi[2][BATCH_ * HID];   // h quantized to fp16, double-buffered
// Wh^T, gate-permuted, fp16: permuted col p = nb*64 + w_n*32 + gate*8 + q
__device__ __half g_W_hi[(size_t)FOURH * HID];

// ---------------- helpers (all sm_80+ base-target PTX) ----------------------
__device__ __forceinline__ uint32_t sw128(uint32_t x) { return x ^ ((x >> 3) & 0x70); }

__device__ __forceinline__ uint32_t smem_u32(const void* p) {
    uint32_t a;
    asm("{ .reg .u64 t; cvta.to.shared.u64 t, %1; cvt.u32.u64 %0, t; }"
        : "=r"(a) : "l"(p));
    return a;
}

__device__ __forceinline__ void cp16(uint32_t d, const void* s) {
    asm volatile("cp.async.cg.shared.global [%0], [%1], 16;"
                 :: "r"(d), "l"(s) : "memory");
}

__device__ __forceinline__ void ldsm4(uint32_t* r, uint32_t a) {
    asm volatile("ldmatrix.sync.aligned.m8n8.x4.shared.b16 {%0,%1,%2,%3}, [%4];"
                 : "=r"(r[0]), "=r"(r[1]), "=r"(r[2]), "=r"(r[3]) : "r"(a));
}

__device__ __forceinline__ void mma16816(float* c, const uint32_t* a,
                                         uint32_t b0, uint32_t b1) {
    asm volatile(
        "mma.sync.aligned.m16n8k16.row.col.f32.f16.f16.f32 "
        "{%0,%1,%2,%3}, {%4,%5,%6,%7}, {%8,%9}, {%0,%1,%2,%3};"
        : "+f"(c[0]), "+f"(c[1]), "+f"(c[2]), "+f"(c[3])
        : "r"(a[0]), "r"(a[1]), "r"(a[2]), "r"(a[3]), "r"(b0), "r"(b1));
}

__device__ __forceinline__ float fast_sigmoid(float v) {
    return __fdividef(1.0f, 1.0f + __expf(-v));
}
__device__ __forceinline__ float fast_tanh(float v) {
    float a = fabsf(v);
    float t = __expf(-2.0f * a);
    float r = __fdividef(1.0f - t, 1.0f + t);
    return copysignf(r, v);
}

// smem stage (32KB): A [sub0 8K | sub1 8K] | B [sub0 8K | sub1 8K]
#define AHI_O 0
#define BHI_O 16384
#define SUB_B 8192
#define STAGE_B 32768
#define NSTAGE 3
#define SMEM_TOTAL (NSTAGE * STAGE_B)   // 98304 per CTA; 2 CTAs/SM = 192K

// ---------------- init: coalesced tiled transpose of Wh into fp16 -----------
__global__ __launch_bounds__(256) void init_w_kernel(const float* __restrict__ Wh) {
    __shared__ float tile[64][65];
    const int cb = blockIdx.x >> 5;        // 0..127  (colp tile /64)
    const int kb = blockIdx.x & 31;        // 0..31   (k tile /64)
    const int tid = threadIdx.x;

    {
        const int k_local = tid >> 2;      // 0..63
        const int seg0 = tid & 3;
        const size_t krow = (size_t)(kb * 64 + k_local) * FOURH;
        #pragma unroll
        for (int ss = 0; ss < 2; ss++) {
            const int s = seg0 + ss * 4;   // 0..7
            const int w_n = s >> 2;
            const int gate = s & 3;
            const int base_o = gate * HID + cb * 16 + w_n * 8;
            const float4 v0 = *(const float4*)(Wh + krow + base_o);
            const float4 v1 = *(const float4*)(Wh + krow + base_o + 4);
            const int r0 = w_n * 32 + gate * 8;
            tile[r0 + 0][k_local] = v0.x;
            tile[r0 + 1][k_local] = v0.y;
            tile[r0 + 2][k_local] = v0.z;
            tile[r0 + 3][k_local] = v0.w;
            tile[r0 + 4][k_local] = v1.x;
            tile[r0 + 5][k_local] = v1.y;
            tile[r0 + 6][k_local] = v1.z;
            tile[r0 + 7][k_local] = v1.w;
        }
    }
    __syncthreads();

    {
        const int r  = tid >> 2;           // 0..63
        const int k0 = (tid & 3) * 16;
        const size_t obase = (size_t)(cb * 64 + r) * HID + kb * 64 + k0;
        __half hibuf[16];
        #pragma unroll
        for (int i = 0; i < 16; i++)
            hibuf[i] = __float2half(tile[r][k0 + i]);
        *(uint4*)(g_W_hi + obase)     = *(uint4*)(hibuf);
        *(uint4*)(g_W_hi + obase + 8) = *(uint4*)(hibuf + 8);
    }
}

__global__ void zero_kernel() {
    const int n = BATCH_ * HID;
    for (int i = blockIdx.x * blockDim.x + threadIdx.x; i < n;
         i += gridDim.x * blockDim.x) {
        g_c[i] = 0.0f;
        g_h_hi[0][i] = __float2half(0.0f);
    }
}

// ---------------- one LSTM timestep ------------------------------------------
// z = h_fp16 @ W_fp16. Grid 256 = 128 N-blocks x 2 M-blocks; 2 CTAs/SM.
// 128 threads = 4 warps, warp grid 2x2, warp tile m32 x n32 (n32 = 4 gates x 8).
__global__ __launch_bounds__(128, 2) void step_kernel(
    const float* __restrict__ x, const float* __restrict__ Wx,
    const float* __restrict__ bvec, int t)
{
    extern __shared__ __align__(1024) unsigned char smem[];
    const uint32_t sb = smem_u32(smem);
    const int tid  = threadIdx.x;
    const int w    = tid >> 5;
    const int lane = tid & 31;
    const int w_m  = w >> 1;          // 0..1 (row group of 32)
    const int w_n  = w & 1;           // 0..1 (col group of 32)
    const int nblk = blockIdx.x >> 1;
    const int mblk = blockIdx.x & 1;
    const int row0 = mblk * 64;       // CTA's batch-row base

    const int par0 = t & 1;
    const int par1 = (t + 1) & 1;

    // -------- cp.async mappings: 128 thr -> 16 rows x 8 k-segments ----------
    const int r0l = tid >> 3;                 // 0..15
    const int kk0 = (tid & 7) * 8;            // 0..56
    uint32_t so[4];
    #pragma unroll
    for (int i = 0; i < 4; i++)
        so[i] = sw128((uint32_t)(r0l + i * 16) * 128 + kk0 * 2);
    const __half* __restrict__ pAh = g_h_hi[par0] + (size_t)(row0 + r0l) * HID + kk0;
    const __half* __restrict__ pBh = g_W_hi + (size_t)(nblk * 64 + r0l) * HID + kk0;
    const size_t rstep16 = (size_t)16 * HID;

    // -------- hoisted epilogue operands --------------------------------------
    const int q2 = (lane & 3) * 2;
    const int hcol0 = nblk * 16 + w_n * 8 + q2;
    float wx[4][2], bb[4][2];
    #pragma unroll
    for (int g = 0; g < 4; g++) {
        const int o = g * HID + hcol0;
        wx[g][0] = Wx[o];     wx[g][1] = Wx[o + 1];
        bb[g][0] = bvec[o];   bb[g][1] = bvec[o + 1];
    }
    const int rbase = row0 + w_m * 32 + (lane >> 2);
    float xt[2][2];
    #pragma unroll
    for (int m = 0; m < 2; m++)
        #pragma unroll
        for (int rh = 0; rh < 2; rh++)
            xt[m][rh] = x[(rbase + m * 16 + rh * 8) * TLEN + t];

    // -------- precomputed ldsm swizzled base offsets --------------------------
    const int lm = lane & 15;
    const int lh = lane >> 4;
    const uint32_t kb_lane = (uint32_t)lh * 16;
    uint32_t roA[2], roB[2];
    #pragma unroll
    for (int m = 0; m < 2; m++)
        roA[m] = (AHI_O + sw128((uint32_t)(w_m * 32 + m * 16 + lm) * 128)) ^ kb_lane;
    #pragma unroll
    for (int gg = 0; gg < 2; gg++)
        roB[gg] = (BHI_O + sw128((uint32_t)(w_n * 32 + gg * 16 + lm) * 128)) ^ kb_lane;

    float cacc[2][4][4];
    #pragma unroll
    for (int m = 0; m < 2; m++)
        #pragma unroll
        for (int g = 0; g < 4; g++)
            #pragma unroll
            for (int i = 0; i < 4; i++) cacc[m][g][i] = 0.0f;

    // -------- chunk issue: K=128 (two 64-k sub-tiles), 16 cp16/thread --------
    auto issue_chunk = [&](uint32_t st, int c) {
        const int ko = c * BKC;
        #pragma unroll
        for (int s2 = 0; s2 < 2; s2++) {
            const int kof = ko + s2 * 64;
            const uint32_t sof = st + s2 * SUB_B;
            #pragma unroll
            for (int i = 0; i < 4; i++) {
                cp16(sof + AHI_O + so[i], pAh + kof + i * rstep16);
                cp16(sof + BHI_O + so[i], pBh + kof + i * rstep16);
            }
        }
        asm volatile("cp.async.commit_group;" ::: "memory");
    };

    // prologue: 2 chunks in flight (3 stages, skew 2)
    issue_chunk(sb, 0);
    issue_chunk(sb + STAGE_B, 1);

    uint32_t stage = 0;     // stage holding chunk c
    uint32_t stage2 = 2;    // stage to fill with chunk c+2
    #pragma unroll 1
    for (int c = 0; c < NCHUNK; c++) {
        if (c < NCHUNK - 1)
            asm volatile("cp.async.wait_group 1;" ::: "memory");
        else
            asm volatile("cp.async.wait_group 0;" ::: "memory");
        __syncthreads();

        if (c + 2 < NCHUNK)
            issue_chunk(sb + stage2 * STAGE_B, c + 2);

        const uint32_t st = sb + stage * STAGE_B;
        #pragma unroll
        for (int ks2 = 0; ks2 < 8; ks2++) {
            const uint32_t sub = (ks2 >> 2) * SUB_B;
            const uint32_t kx = (uint32_t)(ks2 & 3) * 32;
            uint32_t ahi[2][4], bhi[2][4];
            #pragma unroll
            for (int m = 0; m < 2; m++)
                ldsm4(ahi[m], st + sub + (roA[m] ^ kx));
            #pragma unroll
            for (int gg = 0; gg < 2; gg++)
                ldsm4(bhi[gg], st + sub + (roB[gg] ^ kx));
            #pragma unroll
            for (int m = 0; m < 2; m++) {
                #pragma unroll
                for (int g = 0; g < 4; g++) {
                    const int gg = g >> 1, pr = g & 1;
                    mma16816(cacc[m][g], ahi[m], bhi[gg][pr], bhi[gg][pr + 2]);
                }
            }
        }
        stage  = (stage == NSTAGE - 1) ? 0 : stage + 1;
        stage2 = (stage2 == NSTAGE - 1) ? 0 : stage2 + 1;
    }

    // ---- fused LSTM epilogue: all 4 gates of (row, hcol) in this thread ----
    #pragma unroll
    for (int m = 0; m < 2; m++) {
        #pragma unroll
        for (int rh = 0; rh < 2; rh++) {
            const int row = rbase + m * 16 + rh * 8;
            const float xv = xt[m][rh];
            const size_t base = (size_t)row * HID + hcol0;
            const float2 cold = *(const float2*)(g_c + base);
            float hv[2], cv[2];
            #pragma unroll
            for (int e = 0; e < 2; e++) {
                const int ri = rh * 2 + e;
                const float zg = cacc[m][0][ri] + xv * wx[0][e] + bb[0][e];
                const float zi = cacc[m][1][ri] + xv * wx[1][e] + bb[1][e];
                const float zf = cacc[m][2][ri] + xv * wx[2][e] + bb[2][e];
                const float zo = cacc[m][3][ri] + xv * wx[3][e] + bb[3][e];
                const float gg = fast_tanh(zg);
                const float ii = fast_sigmoid(zi);
                const float ff = fast_sigmoid(zf);
                const float oo = fast_sigmoid(zo);
                const float co = (e == 0) ? cold.x : cold.y;
                cv[e] = gg * ii + co * ff;
                hv[e] = fast_tanh(cv[e]) * oo;
            }
            *(float2*)(g_c + base) = make_float2(cv[0], cv[1]);
            *(__half2*)(g_h_hi[par1] + base) =
                __halves2half2(__float2half(hv[0]), __float2half(hv[1]));
        }
    }
}

// ---------------- final projection + softmax ---------------------------------
__global__ void proj_kernel(const float* __restrict__ Wph,
                            const float* __restrict__ bp,
                            float* __restrict__ out)
{
    const int row = blockIdx.x;
    const int lane = threadIdx.x;
    const int par = NSTEP & 1;   // 1

    float acc = -1e30f;
    if (lane < 10) {
        acc = bp[lane];
        const size_t base = (size_t)row * HID;
        for (int k = 0; k < HID; k++) {
            acc += __half2float(g_h_hi[par][base + k]) * Wph[k * 10 + lane];
        }
    }
    float m = acc;
    #pragma unroll
    for (int off = 16; off > 0; off >>= 1)
        m = fmaxf(m, __shfl_xor_sync(0xffffffffu, m, off));
    float e = (lane < 10) ? __expf(acc - m) : 0.0f;
    float s = e;
    #pragma unroll
    for (int off = 16; off > 0; off >>= 1)
        s += __shfl_xor_sync(0xffffffffu, s, off);
    if (lane < 10) out[row * 10 + lane] = e / s;
}

extern "C" void kernel_launch(void* const* d_in, const int* in_sizes, int n_in,
                              void* d_out, int out_size) {
    (void)in_sizes; (void)n_in; (void)out_size;
    const float* x   = (const float*)d_in[0];
    const float* Wx  = (const float*)d_in[1];
    const float* Wh  = (const float*)d_in[2];
    const float* b   = (const float*)d_in[3];
    const float* Wph = (const float*)d_in[4];
    const float* bp  = (const float*)d_in[5];
    float* out = (float*)d_out;

    static int attr_set = 0;
    if (!attr_set) {
        cudaFuncSetAttribute(step_kernel,
                             cudaFuncAttributeMaxDynamicSharedMemorySize,
                             SMEM_TOTAL);
        attr_set = 1;
    }

    init_w_kernel<<<4096, 256>>>(Wh);
    zero_kernel<<<256, 256>>>();
    for (int t = 0; t < NSTEP; t++) {
        step_kernel<<<NBLK, 128, SMEM_TOTAL>>>(x, Wx, b, t);
    }
    proj_kernel<<<BATCH_, 32>>>(Wph, bp, out);
}